// round 6
// baseline (speedup 1.0000x reference)
#include <cuda_runtime.h>
#include <math.h>

// Problem constants (validated against in_sizes at launch).
#define NMAX 20000
#define EMAX 640000
#define ETOTMAX (EMAX + NMAX)

// ---------------- device scratch (no allocations allowed) ----------------
__device__ int   g_is64;
__device__ int   g_src[EMAX];
__device__ int   g_dst[EMAX];
__device__ float g_easum[NMAX];
__device__ float g_ealoop[NMAX];
__device__ int   g_cnt[NMAX];
__device__ int   g_cursor[NMAX];
__device__ int   g_off[NMAX + 1];
__device__ int   g_eid[ETOTMAX];
__device__ float g_xl1[NMAX * 256];
__device__ float g_xr1[NMAX * 256];
__device__ float g_h1[NMAX * 256];
__device__ float g_xl2[NMAX * 128];
__device__ float g_xr2[NMAX * 128];
__device__ float g_pool[128];

// Device-side scratch selector (avoids any host-side symbol queries).
__device__ __forceinline__ float* buf_sel(int code) {
    switch (code) {
        case 0:  return g_xl1;
        case 1:  return g_xr1;
        case 2:  return g_h1;
        case 3:  return g_xl2;
        default: return g_xr2;
    }
}

// ---------------- init (graph replays reuse accumulators) ----------------
__global__ void init_kernel(int n) {
    int i = blockIdx.x * blockDim.x + threadIdx.x;
    if (i < n) {
        g_easum[i]  = 0.f;
        g_cursor[i] = 0;
        g_cnt[i]    = 1;   // self-loop pre-counted
    }
    if (i < 128) g_pool[i] = 0.f;
}

// Detect whether edge_index is stored as int64 (little-endian: high words 0)
__global__ void detect_kernel(const int* __restrict__ raw, int E) {
    int nz = 0;
    int lim = (E < 64) ? E : 64;
    for (int i = threadIdx.x; i < lim; i += 32)
        if (raw[2 * i + 1] != 0) nz = 1;
    nz = __any_sync(0xffffffffu, nz);
    if (threadIdx.x == 0) g_is64 = nz ? 0 : 1;
}

// Extract src/dst, accumulate per-dst edge_attr sum / CSR counts
__global__ void extract_kernel(const int* __restrict__ raw,
                               const float* __restrict__ ea, int E) {
    int e = blockIdx.x * blockDim.x + threadIdx.x;
    if (e >= E) return;
    int is64 = g_is64;
    int s = is64 ? raw[2 * e]       : raw[e];
    int d = is64 ? raw[2 * (E + e)] : raw[E + e];
    g_src[e] = s;
    g_dst[e] = d;
    atomicAdd(&g_easum[d], ea[e]);
    atomicAdd(&g_cnt[d], 1);
}

__global__ void ealoop_kernel(int n) {
    int i = blockIdx.x * blockDim.x + threadIdx.x;
    if (i < n) {
        float deg = (float)(g_cnt[i] - 1);   // real incoming degree
        g_ealoop[i] = g_easum[i] / fmaxf(deg, 1.0f);
    }
}

// Single-block exclusive prefix sum over g_cnt -> g_off
__global__ void scan_kernel(int n) {
    __shared__ int sh[1024];
    __shared__ int carry;
    int tid = threadIdx.x;
    if (tid == 0) carry = 0;
    __syncthreads();
    for (int base = 0; base < n; base += 1024) {
        int i = base + tid;
        int v = (i < n) ? g_cnt[i] : 0;
        sh[tid] = v;
        __syncthreads();
        for (int o = 1; o < 1024; o <<= 1) {
            int t = (tid >= o) ? sh[tid - o] : 0;
            __syncthreads();
            sh[tid] += t;
            __syncthreads();
        }
        if (i < n) g_off[i] = carry + sh[tid] - v;
        __syncthreads();
        if (tid == 0) carry += sh[1023];
        __syncthreads();
    }
    if (tid == 0) g_off[n] = carry;
}

// Fill CSR edge-id lists (edge k<E: real edge; k>=E: self loop of node k-E)
__global__ void scatter_kernel(int E, int n) {
    int k = blockIdx.x * blockDim.x + threadIdx.x;
    int tot = E + n;
    if (k >= tot) return;
    int d = (k < E) ? g_dst[k] : (k - E);
    int pos = g_off[d] + atomicAdd(&g_cursor[d], 1);
    g_eid[pos] = k;
}

// ---- fp32 SGEMM 128x128 tile, 8x8/thread, k-panel 8, dual-weight (z) ----
__global__ void __launch_bounds__(256, 2)
gemm_bias_dual(const float* __restrict__ Ain, int Acode,
               const float* __restrict__ W0, const float* __restrict__ b0, int C0code,
               const float* __restrict__ W1, const float* __restrict__ b1, int C1code,
               int M, int K, int Nn) {
    const float* A = (Acode >= 0) ? buf_sel(Acode) : Ain;
    const float* W    = (blockIdx.z == 0) ? W0 : W1;
    const float* bias = (blockIdx.z == 0) ? b0 : b1;
    float* C = buf_sel(blockIdx.z == 0 ? C0code : C1code);

    __shared__ __align__(16) float As[8][132];   // transposed A panel, padded
    __shared__ __align__(16) float Bs[8][128];

    const int tid = threadIdx.x;
    const int tx = tid & 15, ty = tid >> 4;
    const int tm0 = ty * 8, tn0 = tx * 8;
    const int row0 = blockIdx.x * 128, col0 = blockIdx.y * 128;

    const int arow = tid >> 1;            // 0..127
    const int acol = (tid & 1) * 4;       // 0 or 4
    const int b_r = tid >> 5;             // 0..7
    const int b_c = (tid & 31) * 4;       // 0..124

    const int a_gr = row0 + arow;
    const bool a_ok = (a_gr < M);

    float acc[8][8];
    #pragma unroll
    for (int i = 0; i < 8; i++)
        #pragma unroll
        for (int j = 0; j < 8; j++) acc[i][j] = 0.f;

    for (int k0 = 0; k0 < K; k0 += 8) {
        float4 av = make_float4(0.f, 0.f, 0.f, 0.f);
        if (a_ok) av = *(const float4*)&A[(size_t)a_gr * K + k0 + acol];
        float4 bv = *(const float4*)&W[(size_t)(k0 + b_r) * Nn + col0 + b_c];
        As[acol + 0][arow] = av.x;
        As[acol + 1][arow] = av.y;
        As[acol + 2][arow] = av.z;
        As[acol + 3][arow] = av.w;
        *(float4*)&Bs[b_r][b_c] = bv;
        __syncthreads();

        #pragma unroll
        for (int kk = 0; kk < 8; kk++) {
            float a[8], b[8];
            *(float4*)&a[0] = *(const float4*)&As[kk][tm0];
            *(float4*)&a[4] = *(const float4*)&As[kk][tm0 + 4];
            *(float4*)&b[0] = *(const float4*)&Bs[kk][tn0];
            *(float4*)&b[4] = *(const float4*)&Bs[kk][tn0 + 4];
            #pragma unroll
            for (int i = 0; i < 8; i++)
                #pragma unroll
                for (int j = 0; j < 8; j++)
                    acc[i][j] += a[i] * b[j];
        }
        __syncthreads();
    }

    float bcache[8];
    #pragma unroll
    for (int j = 0; j < 8; j++) bcache[j] = bias[col0 + tn0 + j];
    #pragma unroll
    for (int i = 0; i < 8; i++) {
        int gr = row0 + tm0 + i;
        if (gr >= M) continue;
        float4 v0 = make_float4(acc[i][0] + bcache[0], acc[i][1] + bcache[1],
                                acc[i][2] + bcache[2], acc[i][3] + bcache[3]);
        float4 v1 = make_float4(acc[i][4] + bcache[4], acc[i][5] + bcache[5],
                                acc[i][6] + bcache[6], acc[i][7] + bcache[7]);
        *(float4*)&C[(size_t)gr * Nn + col0 + tn0]     = v0;
        *(float4*)&C[(size_t)gr * Nn + col0 + tn0 + 4] = v1;
    }
}

// ===== fused layer-1 score+softmax+aggregate (flash-style) ===============
// Grid: N blocks x 64 threads (2 warps). Thread t owns channels [4t,4t+4).
// Each 8-lane group = one head (8 lanes x 4 ch = 32 ch). Warps independent.
__global__ void __launch_bounds__(64)
fagg1_kernel(const float* __restrict__ We, const float* __restrict__ att,
             const float* __restrict__ bias, const float* __restrict__ ea,
             int E) {
    const int j = blockIdx.x;
    const int t = threadIdx.x;
    const int lane = t & 31;
    const int c0 = 4 * t;

    const int off = g_off[j];
    const int dcnt = g_off[j + 1] - off;

    const float4 Wv = *(const float4*)&We[c0];
    const float4 Av = *(const float4*)&att[c0];
    const float4 xr = *(const float4*)&g_xr1[(size_t)j * 256 + c0];
    const float eal = g_ealoop[j];

    float4 acc = make_float4(0.f, 0.f, 0.f, 0.f);
    float m = -1e30f, ssum = 0.f;

    for (int cs = 0; cs < dcnt; cs += 32) {
        int cl = min(32, dcnt - cs);
        int sreg = 0; float ereg = 0.f;
        if (lane < cl) {
            int k = g_eid[off + cs + lane];
            sreg = (k < E) ? g_src[k] : j;
            ereg = (k < E) ? ea[k] : eal;
        }
        int e = 0;
        for (; e + 2 <= cl; e += 2) {
            int   s0 = __shfl_sync(0xffffffffu, sreg, e);
            int   s1 = __shfl_sync(0xffffffffu, sreg, e + 1);
            float e0 = __shfl_sync(0xffffffffu, ereg, e);
            float e1 = __shfl_sync(0xffffffffu, ereg, e + 1);
            float4 x0 = *(const float4*)&g_xl1[(size_t)s0 * 256 + c0];
            float4 x1 = *(const float4*)&g_xl1[(size_t)s1 * 256 + c0];
            // partial scores (4 channels each)
            float p0, p1;
            {
                float a = x0.x + xr.x + e0 * Wv.x; a = fmaxf(a,0.f) + 0.2f*fminf(a,0.f);
                float b = x0.y + xr.y + e0 * Wv.y; b = fmaxf(b,0.f) + 0.2f*fminf(b,0.f);
                float c = x0.z + xr.z + e0 * Wv.z; c = fmaxf(c,0.f) + 0.2f*fminf(c,0.f);
                float d = x0.w + xr.w + e0 * Wv.w; d = fmaxf(d,0.f) + 0.2f*fminf(d,0.f);
                p0 = a*Av.x + b*Av.y + c*Av.z + d*Av.w;
            }
            {
                float a = x1.x + xr.x + e1 * Wv.x; a = fmaxf(a,0.f) + 0.2f*fminf(a,0.f);
                float b = x1.y + xr.y + e1 * Wv.y; b = fmaxf(b,0.f) + 0.2f*fminf(b,0.f);
                float c = x1.z + xr.z + e1 * Wv.z; c = fmaxf(c,0.f) + 0.2f*fminf(c,0.f);
                float d = x1.w + xr.w + e1 * Wv.w; d = fmaxf(d,0.f) + 0.2f*fminf(d,0.f);
                p1 = a*Av.x + b*Av.y + c*Av.z + d*Av.w;
            }
            // segmented reduce over the 8-lane head group (two chains overlap)
            p0 += __shfl_xor_sync(0xffffffffu, p0, 1);
            p1 += __shfl_xor_sync(0xffffffffu, p1, 1);
            p0 += __shfl_xor_sync(0xffffffffu, p0, 2);
            p1 += __shfl_xor_sync(0xffffffffu, p1, 2);
            p0 += __shfl_xor_sync(0xffffffffu, p0, 4);
            p1 += __shfl_xor_sync(0xffffffffu, p1, 4);
            // online softmax updates (sequential)
            {
                float nm = fmaxf(m, p0);
                float sc = __expf(m - nm), w = __expf(p0 - nm);
                acc.x = acc.x * sc + w * x0.x;
                acc.y = acc.y * sc + w * x0.y;
                acc.z = acc.z * sc + w * x0.z;
                acc.w = acc.w * sc + w * x0.w;
                ssum = ssum * sc + w;
                m = nm;
            }
            {
                float nm = fmaxf(m, p1);
                float sc = __expf(m - nm), w = __expf(p1 - nm);
                acc.x = acc.x * sc + w * x1.x;
                acc.y = acc.y * sc + w * x1.y;
                acc.z = acc.z * sc + w * x1.z;
                acc.w = acc.w * sc + w * x1.w;
                ssum = ssum * sc + w;
                m = nm;
            }
        }
        for (; e < cl; e++) {
            int   s0 = __shfl_sync(0xffffffffu, sreg, e);
            float e0 = __shfl_sync(0xffffffffu, ereg, e);
            float4 x0 = *(const float4*)&g_xl1[(size_t)s0 * 256 + c0];
            float a = x0.x + xr.x + e0 * Wv.x; a = fmaxf(a,0.f) + 0.2f*fminf(a,0.f);
            float b = x0.y + xr.y + e0 * Wv.y; b = fmaxf(b,0.f) + 0.2f*fminf(b,0.f);
            float c = x0.z + xr.z + e0 * Wv.z; c = fmaxf(c,0.f) + 0.2f*fminf(c,0.f);
            float d = x0.w + xr.w + e0 * Wv.w; d = fmaxf(d,0.f) + 0.2f*fminf(d,0.f);
            float p0 = a*Av.x + b*Av.y + c*Av.z + d*Av.w;
            p0 += __shfl_xor_sync(0xffffffffu, p0, 1);
            p0 += __shfl_xor_sync(0xffffffffu, p0, 2);
            p0 += __shfl_xor_sync(0xffffffffu, p0, 4);
            float nm = fmaxf(m, p0);
            float sc = __expf(m - nm), w = __expf(p0 - nm);
            acc.x = acc.x * sc + w * x0.x;
            acc.y = acc.y * sc + w * x0.y;
            acc.z = acc.z * sc + w * x0.z;
            acc.w = acc.w * sc + w * x0.w;
            ssum = ssum * sc + w;
            m = nm;
        }
    }

    float inv = 1.0f / (ssum + 1e-16f);
    float4 bv = *(const float4*)&bias[c0];
    float4 o;
    o.x = fmaxf(acc.x * inv + bv.x, 0.f);
    o.y = fmaxf(acc.y * inv + bv.y, 0.f);
    o.z = fmaxf(acc.z * inv + bv.z, 0.f);
    o.w = fmaxf(acc.w * inv + bv.w, 0.f);
    *(float4*)&g_h1[(size_t)j * 256 + c0] = o;
}

// ===== fused layer-2 score+softmax+aggregate + pooled accumulation =======
// Grid: N blocks x 32 threads (1 warp). Lane l owns channels [4l,4l+4).
__global__ void __launch_bounds__(32)
fagg2_kernel(const float* __restrict__ We, const float* __restrict__ att,
             const float* __restrict__ bias, const float* __restrict__ ea,
             int E) {
    const int j = blockIdx.x;
    const int lane = threadIdx.x;
    const int c0 = 4 * lane;

    const int off = g_off[j];
    const int dcnt = g_off[j + 1] - off;

    const float4 Wv = *(const float4*)&We[c0];
    const float4 Av = *(const float4*)&att[c0];
    const float4 xr = *(const float4*)&g_xr2[(size_t)j * 128 + c0];
    const float eal = g_ealoop[j];

    float4 acc = make_float4(0.f, 0.f, 0.f, 0.f);
    float m = -1e30f, ssum = 0.f;

    for (int cs = 0; cs < dcnt; cs += 32) {
        int cl = min(32, dcnt - cs);
        int sreg = 0; float ereg = 0.f;
        if (lane < cl) {
            int k = g_eid[off + cs + lane];
            sreg = (k < E) ? g_src[k] : j;
            ereg = (k < E) ? ea[k] : eal;
        }
        int e = 0;
        for (; e + 2 <= cl; e += 2) {
            int   s0 = __shfl_sync(0xffffffffu, sreg, e);
            int   s1 = __shfl_sync(0xffffffffu, sreg, e + 1);
            float e0 = __shfl_sync(0xffffffffu, ereg, e);
            float e1 = __shfl_sync(0xffffffffu, ereg, e + 1);
            float4 x0 = *(const float4*)&g_xl2[(size_t)s0 * 128 + c0];
            float4 x1 = *(const float4*)&g_xl2[(size_t)s1 * 128 + c0];
            float p0, p1;
            {
                float a = x0.x + xr.x + e0 * Wv.x; a = fmaxf(a,0.f) + 0.2f*fminf(a,0.f);
                float b = x0.y + xr.y + e0 * Wv.y; b = fmaxf(b,0.f) + 0.2f*fminf(b,0.f);
                float c = x0.z + xr.z + e0 * Wv.z; c = fmaxf(c,0.f) + 0.2f*fminf(c,0.f);
                float d = x0.w + xr.w + e0 * Wv.w; d = fmaxf(d,0.f) + 0.2f*fminf(d,0.f);
                p0 = a*Av.x + b*Av.y + c*Av.z + d*Av.w;
            }
            {
                float a = x1.x + xr.x + e1 * Wv.x; a = fmaxf(a,0.f) + 0.2f*fminf(a,0.f);
                float b = x1.y + xr.y + e1 * Wv.y; b = fmaxf(b,0.f) + 0.2f*fminf(b,0.f);
                float c = x1.z + xr.z + e1 * Wv.z; c = fmaxf(c,0.f) + 0.2f*fminf(c,0.f);
                float d = x1.w + xr.w + e1 * Wv.w; d = fmaxf(d,0.f) + 0.2f*fminf(d,0.f);
                p1 = a*Av.x + b*Av.y + c*Av.z + d*Av.w;
            }
            #pragma unroll
            for (int o = 1; o < 32; o <<= 1) {
                p0 += __shfl_xor_sync(0xffffffffu, p0, o);
                p1 += __shfl_xor_sync(0xffffffffu, p1, o);
            }
            {
                float nm = fmaxf(m, p0);
                float sc = __expf(m - nm), w = __expf(p0 - nm);
                acc.x = acc.x * sc + w * x0.x;
                acc.y = acc.y * sc + w * x0.y;
                acc.z = acc.z * sc + w * x0.z;
                acc.w = acc.w * sc + w * x0.w;
                ssum = ssum * sc + w;
                m = nm;
            }
            {
                float nm = fmaxf(m, p1);
                float sc = __expf(m - nm), w = __expf(p1 - nm);
                acc.x = acc.x * sc + w * x1.x;
                acc.y = acc.y * sc + w * x1.y;
                acc.z = acc.z * sc + w * x1.z;
                acc.w = acc.w * sc + w * x1.w;
                ssum = ssum * sc + w;
                m = nm;
            }
        }
        for (; e < cl; e++) {
            int   s0 = __shfl_sync(0xffffffffu, sreg, e);
            float e0 = __shfl_sync(0xffffffffu, ereg, e);
            float4 x0 = *(const float4*)&g_xl2[(size_t)s0 * 128 + c0];
            float a = x0.x + xr.x + e0 * Wv.x; a = fmaxf(a,0.f) + 0.2f*fminf(a,0.f);
            float b = x0.y + xr.y + e0 * Wv.y; b = fmaxf(b,0.f) + 0.2f*fminf(b,0.f);
            float c = x0.z + xr.z + e0 * Wv.z; c = fmaxf(c,0.f) + 0.2f*fminf(c,0.f);
            float d = x0.w + xr.w + e0 * Wv.w; d = fmaxf(d,0.f) + 0.2f*fminf(d,0.f);
            float p0 = a*Av.x + b*Av.y + c*Av.z + d*Av.w;
            #pragma unroll
            for (int o = 1; o < 32; o <<= 1)
                p0 += __shfl_xor_sync(0xffffffffu, p0, o);
            float nm = fmaxf(m, p0);
            float sc = __expf(m - nm), w = __expf(p0 - nm);
            acc.x = acc.x * sc + w * x0.x;
            acc.y = acc.y * sc + w * x0.y;
            acc.z = acc.z * sc + w * x0.z;
            acc.w = acc.w * sc + w * x0.w;
            ssum = ssum * sc + w;
            m = nm;
        }
    }

    float inv = 1.0f / (ssum + 1e-16f);
    float4 bv = *(const float4*)&bias[c0];
    atomicAdd(&g_pool[c0 + 0], fmaxf(acc.x * inv + bv.x, 0.f));
    atomicAdd(&g_pool[c0 + 1], fmaxf(acc.y * inv + bv.y, 0.f));
    atomicAdd(&g_pool[c0 + 2], fmaxf(acc.z * inv + bv.z, 0.f));
    atomicAdd(&g_pool[c0 + 3], fmaxf(acc.w * inv + bv.w, 0.f));
}

// ---------------- final: mean, softmax, sigmoid(alpha) -------------------
__global__ void final_kernel(const float* __restrict__ alpha_in,
                             float* __restrict__ out, int out_size, float invN) {
    __shared__ float sh[128];
    int t = threadIdx.x;
    float v = g_pool[t] * invN;
    sh[t] = v;
    __syncthreads();
    for (int o = 64; o; o >>= 1) {
        if (t < o) sh[t] = fmaxf(sh[t], sh[t + o]);
        __syncthreads();
    }
    float mx = sh[0];
    __syncthreads();
    float e = __expf(v - mx);
    sh[t] = e;
    __syncthreads();
    for (int o = 64; o; o >>= 1) {
        if (t < o) sh[t] += sh[t + o];
        __syncthreads();
    }
    float s = sh[0];
    out[t] = e / s;
    if (t == 0 && out_size > 128)
        out[128] = 1.0f / (1.0f + __expf(-alpha_in[0]));
}

// -------------------------------------------------------------------------
extern "C" void kernel_launch(void* const* d_in, const int* in_sizes, int n_in,
                              void* d_out, int out_size) {
    (void)n_in;
    const float* x     = (const float*)d_in[0];
    const int*   eidx  = (const int*)d_in[1];   // int32 or int64 (detected)
    const float* ea    = (const float*)d_in[2];
    const float* W1l   = (const float*)d_in[3];
    const float* b1l   = (const float*)d_in[4];
    const float* W1r   = (const float*)d_in[5];
    const float* b1r   = (const float*)d_in[6];
    const float* We1   = (const float*)d_in[7];
    const float* att1  = (const float*)d_in[8];
    const float* bias1 = (const float*)d_in[9];
    const float* W2l   = (const float*)d_in[10];
    const float* b2l   = (const float*)d_in[11];
    const float* W2r   = (const float*)d_in[12];
    const float* b2r   = (const float*)d_in[13];
    const float* We2   = (const float*)d_in[14];
    const float* att2  = (const float*)d_in[15];
    const float* bias2 = (const float*)d_in[16];
    const float* alpha = (const float*)d_in[17];
    float* out = (float*)d_out;

    int N = in_sizes[0] / 128;
    if (N > NMAX) N = NMAX;
    int E = in_sizes[1] / 2;
    if (E > EMAX) E = EMAX;
    int Etot = E + N;

    // graph preprocessing
    init_kernel<<<(N + 255) / 256, 256>>>(N);
    detect_kernel<<<1, 32>>>(eidx, E);
    extract_kernel<<<(E + 255) / 256, 256>>>(eidx, ea, E);
    ealoop_kernel<<<(N + 255) / 256, 256>>>(N);
    scan_kernel<<<1, 1024>>>(N);
    scatter_kernel<<<(Etot + 255) / 256, 256>>>(E, N);

    int mb = (N + 127) / 128;

    // layer 1: xl1 = x@W1l+b1l, xr1 = x@W1r+b1r (one dual launch)
    gemm_bias_dual<<<dim3(mb, 2, 2), 256>>>(x, -1, W1l, b1l, 0, W1r, b1r, 1,
                                            N, 128, 256);
    fagg1_kernel<<<N, 64>>>(We1, att1, bias1, ea, E);

    // layer 2: xl2 = h1@W2l+b2l, xr2 = h1@W2r+b2r
    gemm_bias_dual<<<dim3(mb, 1, 2), 256>>>(nullptr, 2, W2l, b2l, 3, W2r, b2r, 4,
                                            N, 256, 128);
    fagg2_kernel<<<N, 32>>>(We2, att2, bias2, ea, E);

    // pooled softmax + sigmoid(alpha)
    final_kernel<<<1, 128>>>(alpha, out, out_size, 1.0f / (float)N);
}

// round 8
// speedup vs baseline: 1.1340x; 1.1340x over previous
#include <cuda_runtime.h>
#include <math.h>

// Problem constants (validated against in_sizes at launch).
#define NMAX 20000
#define EMAX 640000
#define ETOTMAX (EMAX + NMAX)

// ---------------- device scratch (no allocations allowed) ----------------
__device__ int   g_is64;
__device__ int   g_src[EMAX];
__device__ int   g_dst[EMAX];
__device__ float g_easum[NMAX];
__device__ float g_ealoop[NMAX];
__device__ int   g_cnt[NMAX];
__device__ int   g_cursor[NMAX];
__device__ int   g_off[NMAX + 1];
__device__ int   g_eid[ETOTMAX];
__device__ float g_xl1[NMAX * 256];
__device__ float g_xr1[NMAX * 256];
__device__ float g_h1[NMAX * 256];
__device__ float g_xl2[NMAX * 128];
__device__ float g_xr2[NMAX * 128];
__device__ float g_s1[(size_t)ETOTMAX * 8];
__device__ float g_s2[ETOTMAX];
__device__ float g_pool[128];

// Device-side scratch selector (avoids any host-side symbol queries).
__device__ __forceinline__ float* buf_sel(int code) {
    switch (code) {
        case 0:  return g_xl1;
        case 1:  return g_xr1;
        case 2:  return g_h1;
        case 3:  return g_xl2;
        default: return g_xr2;
    }
}

// ---------------- init (graph replays reuse accumulators) ----------------
__global__ void init_kernel(int n) {
    int i = blockIdx.x * blockDim.x + threadIdx.x;
    if (i < n) {
        g_easum[i]  = 0.f;
        g_cursor[i] = 0;
        g_cnt[i]    = 1;   // self-loop pre-counted
    }
    if (i < 128) g_pool[i] = 0.f;
}

// Detect whether edge_index is stored as int64 (little-endian: high words 0)
__global__ void detect_kernel(const int* __restrict__ raw, int E) {
    int nz = 0;
    int lim = (E < 64) ? E : 64;
    for (int i = threadIdx.x; i < lim; i += 32)
        if (raw[2 * i + 1] != 0) nz = 1;
    nz = __any_sync(0xffffffffu, nz);
    if (threadIdx.x == 0) g_is64 = nz ? 0 : 1;
}

// Extract src/dst, accumulate per-dst edge_attr sum / CSR counts
__global__ void extract_kernel(const int* __restrict__ raw,
                               const float* __restrict__ ea, int E) {
    int e = blockIdx.x * blockDim.x + threadIdx.x;
    if (e >= E) return;
    int is64 = g_is64;
    int s = is64 ? raw[2 * e]       : raw[e];
    int d = is64 ? raw[2 * (E + e)] : raw[E + e];
    g_src[e] = s;
    g_dst[e] = d;
    atomicAdd(&g_easum[d], ea[e]);
    atomicAdd(&g_cnt[d], 1);
}

__global__ void ealoop_kernel(int n) {
    int i = blockIdx.x * blockDim.x + threadIdx.x;
    if (i < n) {
        float deg = (float)(g_cnt[i] - 1);   // real incoming degree
        g_ealoop[i] = g_easum[i] / fmaxf(deg, 1.0f);
    }
}

// 3-level shuffle scan: 20 elems/thread -> warp scan -> 1 warp over 32 sums.
__global__ void scan_kernel(int n) {
    const int C = 20;                 // 1024*20 = 20480 >= NMAX
    __shared__ int wsum[32];
    __shared__ int gtot;
    int t = threadIdx.x;
    int lane = t & 31, warp = t >> 5;
    int base = t * C;

    int vex[C];
    int run = 0;
    #pragma unroll
    for (int i = 0; i < C; i++) {
        int idx = base + i;
        int x = (idx < n) ? g_cnt[idx] : 0;
        vex[i] = run;                 // exclusive local prefix
        run += x;
    }
    int incl = run;
    #pragma unroll
    for (int o = 1; o < 32; o <<= 1) {
        int u = __shfl_up_sync(0xffffffffu, incl, o);
        if (lane >= o) incl += u;
    }
    if (lane == 31) wsum[warp] = incl;
    __syncthreads();
    if (warp == 0) {
        int s = wsum[lane];
        int si = s;
        #pragma unroll
        for (int o = 1; o < 32; o <<= 1) {
            int u = __shfl_up_sync(0xffffffffu, si, o);
            if (lane >= o) si += u;
        }
        wsum[lane] = si - s;          // exclusive warp prefix
        if (lane == 31) gtot = si;
    }
    __syncthreads();
    int pre = wsum[warp] + (incl - run);
    #pragma unroll
    for (int i = 0; i < C; i++) {
        int idx = base + i;
        if (idx < n) g_off[idx] = pre + vex[i];
    }
    if (t == 0) g_off[n] = gtot;
}

// Fill CSR edge-id lists (edge k<E: real edge; k>=E: self loop of node k-E)
__global__ void scatter_kernel(int E, int n) {
    int k = blockIdx.x * blockDim.x + threadIdx.x;
    int tot = E + n;
    if (k >= tot) return;
    int d = (k < E) ? g_dst[k] : (k - E);
    int pos = g_off[d] + atomicAdd(&g_cursor[d], 1);
    g_eid[pos] = k;
}

// ---- fp32 SGEMM 128x128 tile, 8x8/thread, k-panel 8, dual-weight (z) ----
__global__ void __launch_bounds__(256, 2)
gemm_bias_dual(const float* __restrict__ Ain, int Acode,
               const float* __restrict__ W0, const float* __restrict__ b0, int C0code,
               const float* __restrict__ W1, const float* __restrict__ b1, int C1code,
               int M, int K, int Nn) {
    const float* A = (Acode >= 0) ? buf_sel(Acode) : Ain;
    const float* W    = (blockIdx.z == 0) ? W0 : W1;
    const float* bias = (blockIdx.z == 0) ? b0 : b1;
    float* C = buf_sel(blockIdx.z == 0 ? C0code : C1code);

    __shared__ __align__(16) float As[8][132];   // transposed A panel, padded
    __shared__ __align__(16) float Bs[8][128];

    const int tid = threadIdx.x;
    const int tx = tid & 15, ty = tid >> 4;
    const int tm0 = ty * 8, tn0 = tx * 8;
    const int row0 = blockIdx.x * 128, col0 = blockIdx.y * 128;

    const int arow = tid >> 1;            // 0..127
    const int acol = (tid & 1) * 4;       // 0 or 4
    const int b_r = tid >> 5;             // 0..7
    const int b_c = (tid & 31) * 4;       // 0..124

    const int a_gr = row0 + arow;
    const bool a_ok = (a_gr < M);

    float acc[8][8];
    #pragma unroll
    for (int i = 0; i < 8; i++)
        #pragma unroll
        for (int j = 0; j < 8; j++) acc[i][j] = 0.f;

    for (int k0 = 0; k0 < K; k0 += 8) {
        float4 av = make_float4(0.f, 0.f, 0.f, 0.f);
        if (a_ok) av = *(const float4*)&A[(size_t)a_gr * K + k0 + acol];
        float4 bv = *(const float4*)&W[(size_t)(k0 + b_r) * Nn + col0 + b_c];
        As[acol + 0][arow] = av.x;
        As[acol + 1][arow] = av.y;
        As[acol + 2][arow] = av.z;
        As[acol + 3][arow] = av.w;
        *(float4*)&Bs[b_r][b_c] = bv;
        __syncthreads();

        #pragma unroll
        for (int kk = 0; kk < 8; kk++) {
            float a[8], b[8];
            *(float4*)&a[0] = *(const float4*)&As[kk][tm0];
            *(float4*)&a[4] = *(const float4*)&As[kk][tm0 + 4];
            *(float4*)&b[0] = *(const float4*)&Bs[kk][tn0];
            *(float4*)&b[4] = *(const float4*)&Bs[kk][tn0 + 4];
            #pragma unroll
            for (int i = 0; i < 8; i++)
                #pragma unroll
                for (int j = 0; j < 8; j++)
                    acc[i][j] += a[i] * b[j];
        }
        __syncthreads();
    }

    float bcache[8];
    #pragma unroll
    for (int j = 0; j < 8; j++) bcache[j] = bias[col0 + tn0 + j];
    #pragma unroll
    for (int i = 0; i < 8; i++) {
        int gr = row0 + tm0 + i;
        if (gr >= M) continue;
        float4 v0 = make_float4(acc[i][0] + bcache[0], acc[i][1] + bcache[1],
                                acc[i][2] + bcache[2], acc[i][3] + bcache[3]);
        float4 v1 = make_float4(acc[i][4] + bcache[4], acc[i][5] + bcache[5],
                                acc[i][6] + bcache[6], acc[i][7] + bcache[7]);
        *(float4*)&C[(size_t)gr * Nn + col0 + tn0]     = v0;
        *(float4*)&C[(size_t)gr * Nn + col0 + tn0 + 4] = v1;
    }
}

// ---- layer 1 scores (H=8, C=32), warp per CSR slot, lane owns 8 ch ------
// Head h = lanes [4h, 4h+4); segmented 4-lane reduce = 2 shfls per edge.
__global__ void __launch_bounds__(256)
score1_kernel(const float* __restrict__ We, const float* __restrict__ att,
              const float* __restrict__ ea, int E, int Etot) {
    int t = threadIdx.x;
    int warp = t >> 5, lane = t & 31;
    int p = blockIdx.x * 8 + warp;
    if (p >= Etot) return;
    int k = g_eid[p];
    int s, d;
    float eav;
    if (k < E) { s = g_src[k]; d = g_dst[k]; eav = ea[k]; }
    else       { s = d = k - E; eav = g_ealoop[s]; }
    const int c0 = lane * 8;
    float4 W0 = *(const float4*)&We[c0],  W1 = *(const float4*)&We[c0 + 4];
    float4 A0 = *(const float4*)&att[c0], A1 = *(const float4*)&att[c0 + 4];
    float4 l0 = *(const float4*)&g_xl1[(size_t)s * 256 + c0];
    float4 l1 = *(const float4*)&g_xl1[(size_t)s * 256 + c0 + 4];
    float4 r0 = *(const float4*)&g_xr1[(size_t)d * 256 + c0];
    float4 r1 = *(const float4*)&g_xr1[(size_t)d * 256 + c0 + 4];

    float p0;
    {
        float a = l0.x + r0.x + eav * W0.x; a = fmaxf(a,0.f) + 0.2f*fminf(a,0.f);
        float b = l0.y + r0.y + eav * W0.y; b = fmaxf(b,0.f) + 0.2f*fminf(b,0.f);
        float c = l0.z + r0.z + eav * W0.z; c = fmaxf(c,0.f) + 0.2f*fminf(c,0.f);
        float e = l0.w + r0.w + eav * W0.w; e = fmaxf(e,0.f) + 0.2f*fminf(e,0.f);
        p0 = a*A0.x + b*A0.y + c*A0.z + e*A0.w;
        a = l1.x + r1.x + eav * W1.x; a = fmaxf(a,0.f) + 0.2f*fminf(a,0.f);
        b = l1.y + r1.y + eav * W1.y; b = fmaxf(b,0.f) + 0.2f*fminf(b,0.f);
        c = l1.z + r1.z + eav * W1.z; c = fmaxf(c,0.f) + 0.2f*fminf(c,0.f);
        e = l1.w + r1.w + eav * W1.w; e = fmaxf(e,0.f) + 0.2f*fminf(e,0.f);
        p0 += a*A1.x + b*A1.y + c*A1.z + e*A1.w;
    }
    p0 += __shfl_xor_sync(0xffffffffu, p0, 1);
    p0 += __shfl_xor_sync(0xffffffffu, p0, 2);
    if ((lane & 3) == 0) g_s1[(size_t)p * 8 + (lane >> 2)] = p0;
}

// ---- layer 2 scores (H=1, C=128), warp per CSR slot, lane owns 4 ch -----
__global__ void __launch_bounds__(256)
score2_kernel(const float* __restrict__ We, const float* __restrict__ att,
              const float* __restrict__ ea, int E, int Etot) {
    int t = threadIdx.x;
    int warp = t >> 5, lane = t & 31;
    int p = blockIdx.x * 8 + warp;
    if (p >= Etot) return;
    int k = g_eid[p];
    int s, d;
    float eav;
    if (k < E) { s = g_src[k]; d = g_dst[k]; eav = ea[k]; }
    else       { s = d = k - E; eav = g_ealoop[s]; }
    const int c0 = lane * 4;
    float4 Wv = *(const float4*)&We[c0];
    float4 Av = *(const float4*)&att[c0];
    float4 lv = *(const float4*)&g_xl2[(size_t)s * 128 + c0];
    float4 rv = *(const float4*)&g_xr2[(size_t)d * 128 + c0];
    float a = lv.x + rv.x + eav * Wv.x; a = fmaxf(a,0.f) + 0.2f*fminf(a,0.f);
    float b = lv.y + rv.y + eav * Wv.y; b = fmaxf(b,0.f) + 0.2f*fminf(b,0.f);
    float c = lv.z + rv.z + eav * Wv.z; c = fmaxf(c,0.f) + 0.2f*fminf(c,0.f);
    float e = lv.w + rv.w + eav * Wv.w; e = fmaxf(e,0.f) + 0.2f*fminf(e,0.f);
    float acc = a*Av.x + b*Av.y + c*Av.z + e*Av.w;
    #pragma unroll
    for (int o = 16; o; o >>= 1) acc += __shfl_xor_sync(0xffffffffu, acc, o);
    if (lane == 0) g_s2[p] = acc;
}

// ---------- layer 1 aggregation: one block (256 thr) per node ------------
__global__ void agg1_kernel(const float* __restrict__ bias, int E) {
    const int CH = 64;
    __shared__ float mx[8], idn[8];
    __shared__ float ash[CH * 8];
    __shared__ int   ssh[CH];
    int j = blockIdx.x;
    int off = g_off[j], end = g_off[j + 1];
    int d = end - off;
    int t = threadIdx.x;
    int h = t >> 5, lane = t & 31;

    // online softmax stats per head (warp h owns head h)
    float m = -1e30f, sum = 0.f;
    for (int idx = lane; idx < d; idx += 32) {
        float sv = g_s1[(size_t)(off + idx) * 8 + h];
        if (sv > m) { sum = sum * __expf(m - sv) + 1.0f; m = sv; }
        else        { sum += __expf(sv - m); }
    }
    #pragma unroll
    for (int o = 16; o; o >>= 1) {
        float m2 = __shfl_xor_sync(0xffffffffu, m, o);
        float s2 = __shfl_xor_sync(0xffffffffu, sum, o);
        float nm = fmaxf(m, m2);
        sum = sum * __expf(m - nm) + s2 * __expf(m2 - nm);
        m = nm;
    }
    if (lane == 0) { mx[h] = m; idn[h] = 1.0f / (sum + 1e-16f); }
    __syncthreads();

    float accv = 0.f;
    for (int cs = 0; cs < d; cs += CH) {
        int cl = min(CH, d - cs);
        for (int i = t; i < cl * 8; i += 256) {
            float sv = g_s1[(size_t)(off + cs) * 8 + i];
            int hh = i & 7;
            ash[i] = __expf(sv - mx[hh]) * idn[hh];
        }
        for (int i = t; i < cl; i += 256) {
            int k = g_eid[off + cs + i];
            ssh[i] = (k < E) ? g_src[k] : (k - E);
        }
        __syncthreads();
        #pragma unroll 4
        for (int el = 0; el < cl; el++) {
            float a = ash[el * 8 + h];
            accv += a * g_xl1[(size_t)ssh[el] * 256 + h * 32 + lane];
        }
        __syncthreads();
    }
    int c = h * 32 + lane;
    g_h1[(size_t)j * 256 + c] = fmaxf(accv + bias[c], 0.f);
}

// ---------- layer 2 aggregation + mean pool: block (128 thr) per node ----
__global__ void agg2_kernel(const float* __restrict__ bias, int E) {
    __shared__ float wm[4], ws[4];
    __shared__ float M0sh, IVsh;
    __shared__ float ash[128];
    __shared__ int   ssh[128];
    int j = blockIdx.x;
    int off = g_off[j], end = g_off[j + 1];
    int d = end - off;
    int t = threadIdx.x;
    int w = t >> 5, lane = t & 31;

    float m = -1e30f, sum = 0.f;
    for (int idx = t; idx < d; idx += 128) {
        float sv = g_s2[off + idx];
        if (sv > m) { sum = sum * __expf(m - sv) + 1.0f; m = sv; }
        else        { sum += __expf(sv - m); }
    }
    #pragma unroll
    for (int o = 16; o; o >>= 1) {
        float m2 = __shfl_xor_sync(0xffffffffu, m, o);
        float s2 = __shfl_xor_sync(0xffffffffu, sum, o);
        float nm = fmaxf(m, m2);
        sum = sum * __expf(m - nm) + s2 * __expf(m2 - nm);
        m = nm;
    }
    if (lane == 0) { wm[w] = m; ws[w] = sum; }
    __syncthreads();
    if (t == 0) {
        float M0 = fmaxf(fmaxf(wm[0], wm[1]), fmaxf(wm[2], wm[3]));
        float S0 = ws[0] * __expf(wm[0] - M0) + ws[1] * __expf(wm[1] - M0)
                 + ws[2] * __expf(wm[2] - M0) + ws[3] * __expf(wm[3] - M0);
        M0sh = M0;
        IVsh = 1.0f / (S0 + 1e-16f);
    }
    __syncthreads();
    float M0 = M0sh, invd = IVsh;

    float accv = 0.f;
    for (int cs = 0; cs < d; cs += 128) {
        int cl = min(128, d - cs);
        if (t < cl) {
            ash[t] = __expf(g_s2[off + cs + t] - M0) * invd;
            int k = g_eid[off + cs + t];
            ssh[t] = (k < E) ? g_src[k] : (k - E);
        }
        __syncthreads();
        #pragma unroll 4
        for (int el = 0; el < cl; el++)
            accv += ash[el] * g_xl2[(size_t)ssh[el] * 128 + t];
        __syncthreads();
    }
    float val = fmaxf(accv + bias[t], 0.f);
    atomicAdd(&g_pool[t], val);
}

// ---------------- final: mean, softmax, sigmoid(alpha) -------------------
__global__ void final_kernel(const float* __restrict__ alpha_in,
                             float* __restrict__ out, int out_size, float invN) {
    __shared__ float sh[128];
    int t = threadIdx.x;
    float v = g_pool[t] * invN;
    sh[t] = v;
    __syncthreads();
    for (int o = 64; o; o >>= 1) {
        if (t < o) sh[t] = fmaxf(sh[t], sh[t + o]);
        __syncthreads();
    }
    float mx = sh[0];
    __syncthreads();
    float e = __expf(v - mx);
    sh[t] = e;
    __syncthreads();
    for (int o = 64; o; o >>= 1) {
        if (t < o) sh[t] += sh[t + o];
        __syncthreads();
    }
    float s = sh[0];
    out[t] = e / s;
    if (t == 0 && out_size > 128)
        out[128] = 1.0f / (1.0f + __expf(-alpha_in[0]));
}

// -------------------------------------------------------------------------
extern "C" void kernel_launch(void* const* d_in, const int* in_sizes, int n_in,
                              void* d_out, int out_size) {
    (void)n_in;
    const float* x     = (const float*)d_in[0];
    const int*   eidx  = (const int*)d_in[1];   // int32 or int64 (detected)
    const float* ea    = (const float*)d_in[2];
    const float* W1l   = (const float*)d_in[3];
    const float* b1l   = (const float*)d_in[4];
    const float* W1r   = (const float*)d_in[5];
    const float* b1r   = (const float*)d_in[6];
    const float* We1   = (const float*)d_in[7];
    const float* att1  = (const float*)d_in[8];
    const float* bias1 = (const float*)d_in[9];
    const float* W2l   = (const float*)d_in[10];
    const float* b2l   = (const float*)d_in[11];
    const float* W2r   = (const float*)d_in[12];
    const float* b2r   = (const float*)d_in[13];
    const float* We2   = (const float*)d_in[14];
    const float* att2  = (const float*)d_in[15];
    const float* bias2 = (const float*)d_in[16];
    const float* alpha = (const float*)d_in[17];
    float* out = (float*)d_out;

    int N = in_sizes[0] / 128;
    if (N > NMAX) N = NMAX;
    int E = in_sizes[1] / 2;
    if (E > EMAX) E = EMAX;
    int Etot = E + N;

    int mb = (N + 127) / 128;

    // preprocessing + layer-1 GEMM placed 4th so ncu (-s 5) captures it
    init_kernel<<<(N + 255) / 256, 256>>>(N);
    detect_kernel<<<1, 32>>>(eidx, E);
    extract_kernel<<<(E + 255) / 256, 256>>>(eidx, ea, E);
    gemm_bias_dual<<<dim3(mb, 2, 2), 256>>>(x, -1, W1l, b1l, 0, W1r, b1r, 1,
                                            N, 128, 256);           // 4th launch
    ealoop_kernel<<<(N + 255) / 256, 256>>>(N);
    scan_kernel<<<1, 1024>>>(N);
    scatter_kernel<<<(Etot + 255) / 256, 256>>>(E, N);

    // layer 1 edge pipeline
    score1_kernel<<<(Etot + 7) / 8, 256>>>(We1, att1, ea, E, Etot);
    agg1_kernel<<<N, 256>>>(bias1, E);

    // layer 2
    gemm_bias_dual<<<dim3(mb, 1, 2), 256>>>(nullptr, 2, W2l, b2l, 3, W2r, b2r, 4,
                                            N, 256, 128);
    score2_kernel<<<(Etot + 7) / 8, 256>>>(We2, att2, ea, E, Etot);
    agg2_kernel<<<N, 128>>>(bias2, E);

    // pooled softmax + sigmoid(alpha)
    final_kernel<<<1, 128>>>(alpha, out, out_size, 1.0f / (float)N);
}

// round 9
// speedup vs baseline: 1.2452x; 1.0980x over previous
#include <cuda_runtime.h>
#include <math.h>

// Problem constants (validated against in_sizes at launch).
#define NMAX 20000
#define EMAX 640000
#define ETOTMAX (EMAX + NMAX)

// ---------------- device scratch (no allocations allowed) ----------------
__device__ int   g_is64;
__device__ int   g_src[EMAX];
__device__ int   g_dst[EMAX];
__device__ float g_easum[NMAX];
__device__ float g_ealoop[NMAX];
__device__ int   g_cnt[NMAX];
__device__ int   g_cursor[NMAX];
__device__ int   g_off[NMAX + 1];
__device__ int   g_eid[ETOTMAX];
__device__ float g_xl1[NMAX * 256];
__device__ float g_xr1[NMAX * 256];
__device__ float g_h1[NMAX * 256];
__device__ float g_xl2[NMAX * 128];
__device__ float g_xr2[NMAX * 128];
__device__ float g_s1[(size_t)ETOTMAX * 8];
__device__ float g_s2[ETOTMAX];
__device__ float g_pool[128];

// Device-side scratch selector (avoids any host-side symbol queries).
__device__ __forceinline__ float* buf_sel(int code) {
    switch (code) {
        case 0:  return g_xl1;
        case 1:  return g_xr1;
        case 2:  return g_h1;
        case 3:  return g_xl2;
        default: return g_xr2;
    }
}

// ---------------- init (graph replays reuse accumulators) ----------------
__global__ void init_kernel(int n) {
    int i = blockIdx.x * blockDim.x + threadIdx.x;
    if (i < n) {
        g_easum[i]  = 0.f;
        g_cursor[i] = 0;
        g_cnt[i]    = 1;   // self-loop pre-counted
    }
    if (i < 128) g_pool[i] = 0.f;
}

// Detect whether edge_index is stored as int64 (little-endian: high words 0)
__global__ void detect_kernel(const int* __restrict__ raw, int E) {
    int nz = 0;
    int lim = (E < 64) ? E : 64;
    for (int i = threadIdx.x; i < lim; i += 32)
        if (raw[2 * i + 1] != 0) nz = 1;
    nz = __any_sync(0xffffffffu, nz);
    if (threadIdx.x == 0) g_is64 = nz ? 0 : 1;
}

// Extract src/dst, accumulate per-dst edge_attr sum / CSR counts
__global__ void extract_kernel(const int* __restrict__ raw,
                               const float* __restrict__ ea, int E) {
    int e = blockIdx.x * blockDim.x + threadIdx.x;
    if (e >= E) return;
    int is64 = g_is64;
    int s = is64 ? raw[2 * e]       : raw[e];
    int d = is64 ? raw[2 * (E + e)] : raw[E + e];
    g_src[e] = s;
    g_dst[e] = d;
    atomicAdd(&g_easum[d], ea[e]);
    atomicAdd(&g_cnt[d], 1);
}

__global__ void ealoop_kernel(int n) {
    int i = blockIdx.x * blockDim.x + threadIdx.x;
    if (i < n) {
        float deg = (float)(g_cnt[i] - 1);   // real incoming degree
        g_ealoop[i] = g_easum[i] / fmaxf(deg, 1.0f);
    }
}

// 3-level shuffle scan: 20 elems/thread -> warp scan -> 1 warp over 32 sums.
__global__ void scan_kernel(int n) {
    const int C = 20;                 // 1024*20 = 20480 >= NMAX
    __shared__ int wsum[32];
    __shared__ int gtot;
    int t = threadIdx.x;
    int lane = t & 31, warp = t >> 5;
    int base = t * C;

    int vex[C];
    int run = 0;
    #pragma unroll
    for (int i = 0; i < C; i++) {
        int idx = base + i;
        int x = (idx < n) ? g_cnt[idx] : 0;
        vex[i] = run;                 // exclusive local prefix
        run += x;
    }
    int incl = run;
    #pragma unroll
    for (int o = 1; o < 32; o <<= 1) {
        int u = __shfl_up_sync(0xffffffffu, incl, o);
        if (lane >= o) incl += u;
    }
    if (lane == 31) wsum[warp] = incl;
    __syncthreads();
    if (warp == 0) {
        int s = wsum[lane];
        int si = s;
        #pragma unroll
        for (int o = 1; o < 32; o <<= 1) {
            int u = __shfl_up_sync(0xffffffffu, si, o);
            if (lane >= o) si += u;
        }
        wsum[lane] = si - s;          // exclusive warp prefix
        if (lane == 31) gtot = si;
    }
    __syncthreads();
    int pre = wsum[warp] + (incl - run);
    #pragma unroll
    for (int i = 0; i < C; i++) {
        int idx = base + i;
        if (idx < n) g_off[idx] = pre + vex[i];
    }
    if (t == 0) g_off[n] = gtot;
}

// Fill CSR edge-id lists (edge k<E: real edge; k>=E: self loop of node k-E)
__global__ void scatter_kernel(int E, int n) {
    int k = blockIdx.x * blockDim.x + threadIdx.x;
    int tot = E + n;
    if (k >= tot) return;
    int d = (k < E) ? g_dst[k] : (k - E);
    int pos = g_off[d] + atomicAdd(&g_cursor[d], 1);
    g_eid[pos] = k;
}

// ---- fp32 SGEMM 128x128, 8x8/thread, k-panel 8, double-buffered smem ----
__global__ void __launch_bounds__(256, 2)
gemm_bias_dual(const float* __restrict__ Ain, int Acode,
               const float* __restrict__ W0, const float* __restrict__ b0, int C0code,
               const float* __restrict__ W1, const float* __restrict__ b1, int C1code,
               int M, int K, int Nn) {
    const float* A = (Acode >= 0) ? buf_sel(Acode) : Ain;
    const float* W    = (blockIdx.z == 0) ? W0 : W1;
    const float* bias = (blockIdx.z == 0) ? b0 : b1;
    float* C = buf_sel(blockIdx.z == 0 ? C0code : C1code);

    __shared__ __align__(16) float As[2][8][132];   // transposed A panel
    __shared__ __align__(16) float Bs[2][8][128];

    const int tid = threadIdx.x;
    const int tx = tid & 15, ty = tid >> 4;
    const int tm0 = ty * 8, tn0 = tx * 8;
    const int row0 = blockIdx.x * 128, col0 = blockIdx.y * 128;

    const int arow = tid >> 1;            // 0..127
    const int acol = (tid & 1) * 4;       // 0 or 4
    const int b_r = tid >> 5;             // 0..7
    const int b_c = (tid & 31) * 4;       // 0..124

    const int a_gr = row0 + arow;
    const bool a_ok = (a_gr < M);
    const int P = K >> 3;

    float acc[8][8];
    #pragma unroll
    for (int i = 0; i < 8; i++)
        #pragma unroll
        for (int j = 0; j < 8; j++) acc[i][j] = 0.f;

    // preload panel 0
    {
        float4 av = make_float4(0.f, 0.f, 0.f, 0.f);
        if (a_ok) av = *(const float4*)&A[(size_t)a_gr * K + acol];
        float4 bv = *(const float4*)&W[(size_t)b_r * Nn + col0 + b_c];
        As[0][acol + 0][arow] = av.x;
        As[0][acol + 1][arow] = av.y;
        As[0][acol + 2][arow] = av.z;
        As[0][acol + 3][arow] = av.w;
        *(float4*)&Bs[0][b_r][b_c] = bv;
    }
    __syncthreads();

    for (int p = 0; p < P; p++) {
        const int cur = p & 1;
        const bool more = (p + 1 < P);
        float4 av_n = make_float4(0.f, 0.f, 0.f, 0.f), bv_n;
        if (more) {
            int k0 = (p + 1) * 8;
            if (a_ok) av_n = *(const float4*)&A[(size_t)a_gr * K + k0 + acol];
            bv_n = *(const float4*)&W[(size_t)(k0 + b_r) * Nn + col0 + b_c];
        }

        #pragma unroll
        for (int kk = 0; kk < 8; kk++) {
            float a[8], b[8];
            *(float4*)&a[0] = *(const float4*)&As[cur][kk][tm0];
            *(float4*)&a[4] = *(const float4*)&As[cur][kk][tm0 + 4];
            *(float4*)&b[0] = *(const float4*)&Bs[cur][kk][tn0];
            *(float4*)&b[4] = *(const float4*)&Bs[cur][kk][tn0 + 4];
            #pragma unroll
            for (int i = 0; i < 8; i++)
                #pragma unroll
                for (int j = 0; j < 8; j++)
                    acc[i][j] += a[i] * b[j];
        }

        if (more) {
            const int nxt = cur ^ 1;
            As[nxt][acol + 0][arow] = av_n.x;
            As[nxt][acol + 1][arow] = av_n.y;
            As[nxt][acol + 2][arow] = av_n.z;
            As[nxt][acol + 3][arow] = av_n.w;
            *(float4*)&Bs[nxt][b_r][b_c] = bv_n;
        }
        __syncthreads();
    }

    float bcache[8];
    #pragma unroll
    for (int j = 0; j < 8; j++) bcache[j] = bias[col0 + tn0 + j];
    #pragma unroll
    for (int i = 0; i < 8; i++) {
        int gr = row0 + tm0 + i;
        if (gr >= M) continue;
        float4 v0 = make_float4(acc[i][0] + bcache[0], acc[i][1] + bcache[1],
                                acc[i][2] + bcache[2], acc[i][3] + bcache[3]);
        float4 v1 = make_float4(acc[i][4] + bcache[4], acc[i][5] + bcache[5],
                                acc[i][6] + bcache[6], acc[i][7] + bcache[7]);
        *(float4*)&C[(size_t)gr * Nn + col0 + tn0]     = v0;
        *(float4*)&C[(size_t)gr * Nn + col0 + tn0 + 4] = v1;
    }
}

// ---- layer 1 scores (H=8, C=32), warp per TWO CSR slots -----------------
// Lane owns 8 channels; head h = lanes [4h,4h+4): 2 shfls per edge.
__global__ void __launch_bounds__(256)
score1_kernel(const float* __restrict__ We, const float* __restrict__ att,
              const float* __restrict__ ea, int E, int Etot) {
    int t = threadIdx.x;
    int warp = t >> 5, lane = t & 31;
    int pb = (blockIdx.x * 8 + warp) * 2;
    if (pb >= Etot) return;
    bool v1 = (pb + 1 < Etot);

    int k0 = g_eid[pb];
    int k1 = v1 ? g_eid[pb + 1] : k0;
    int s0, d0, s1, d1;
    float ev0, ev1;
    if (k0 < E) { s0 = g_src[k0]; d0 = g_dst[k0]; ev0 = ea[k0]; }
    else        { s0 = d0 = k0 - E; ev0 = g_ealoop[s0]; }
    if (k1 < E) { s1 = g_src[k1]; d1 = g_dst[k1]; ev1 = ea[k1]; }
    else        { s1 = d1 = k1 - E; ev1 = g_ealoop[s1]; }

    const int c0 = lane * 8;
    float4 W0 = *(const float4*)&We[c0],  W1 = *(const float4*)&We[c0 + 4];
    float4 A0 = *(const float4*)&att[c0], A1 = *(const float4*)&att[c0 + 4];

    float4 l00 = *(const float4*)&g_xl1[(size_t)s0 * 256 + c0];
    float4 l01 = *(const float4*)&g_xl1[(size_t)s0 * 256 + c0 + 4];
    float4 r00 = *(const float4*)&g_xr1[(size_t)d0 * 256 + c0];
    float4 r01 = *(const float4*)&g_xr1[(size_t)d0 * 256 + c0 + 4];
    float4 l10 = *(const float4*)&g_xl1[(size_t)s1 * 256 + c0];
    float4 l11 = *(const float4*)&g_xl1[(size_t)s1 * 256 + c0 + 4];
    float4 r10 = *(const float4*)&g_xr1[(size_t)d1 * 256 + c0];
    float4 r11 = *(const float4*)&g_xr1[(size_t)d1 * 256 + c0 + 4];

    float p0, p1;
    {
        float a = l00.x + r00.x + ev0 * W0.x; a = fmaxf(a,0.f) + 0.2f*fminf(a,0.f);
        float b = l00.y + r00.y + ev0 * W0.y; b = fmaxf(b,0.f) + 0.2f*fminf(b,0.f);
        float c = l00.z + r00.z + ev0 * W0.z; c = fmaxf(c,0.f) + 0.2f*fminf(c,0.f);
        float e = l00.w + r00.w + ev0 * W0.w; e = fmaxf(e,0.f) + 0.2f*fminf(e,0.f);
        p0 = a*A0.x + b*A0.y + c*A0.z + e*A0.w;
        a = l01.x + r01.x + ev0 * W1.x; a = fmaxf(a,0.f) + 0.2f*fminf(a,0.f);
        b = l01.y + r01.y + ev0 * W1.y; b = fmaxf(b,0.f) + 0.2f*fminf(b,0.f);
        c = l01.z + r01.z + ev0 * W1.z; c = fmaxf(c,0.f) + 0.2f*fminf(c,0.f);
        e = l01.w + r01.w + ev0 * W1.w; e = fmaxf(e,0.f) + 0.2f*fminf(e,0.f);
        p0 += a*A1.x + b*A1.y + c*A1.z + e*A1.w;
    }
    {
        float a = l10.x + r10.x + ev1 * W0.x; a = fmaxf(a,0.f) + 0.2f*fminf(a,0.f);
        float b = l10.y + r10.y + ev1 * W0.y; b = fmaxf(b,0.f) + 0.2f*fminf(b,0.f);
        float c = l10.z + r10.z + ev1 * W0.z; c = fmaxf(c,0.f) + 0.2f*fminf(c,0.f);
        float e = l10.w + r10.w + ev1 * W0.w; e = fmaxf(e,0.f) + 0.2f*fminf(e,0.f);
        p1 = a*A0.x + b*A0.y + c*A0.z + e*A0.w;
        a = l11.x + r11.x + ev1 * W1.x; a = fmaxf(a,0.f) + 0.2f*fminf(a,0.f);
        b = l11.y + r11.y + ev1 * W1.y; b = fmaxf(b,0.f) + 0.2f*fminf(b,0.f);
        c = l11.z + r11.z + ev1 * W1.z; c = fmaxf(c,0.f) + 0.2f*fminf(c,0.f);
        e = l11.w + r11.w + ev1 * W1.w; e = fmaxf(e,0.f) + 0.2f*fminf(e,0.f);
        p1 += a*A1.x + b*A1.y + c*A1.z + e*A1.w;
    }
    p0 += __shfl_xor_sync(0xffffffffu, p0, 1);
    p1 += __shfl_xor_sync(0xffffffffu, p1, 1);
    p0 += __shfl_xor_sync(0xffffffffu, p0, 2);
    p1 += __shfl_xor_sync(0xffffffffu, p1, 2);
    if ((lane & 3) == 0) {
        g_s1[(size_t)pb * 8 + (lane >> 2)] = p0;
        if (v1) g_s1[(size_t)(pb + 1) * 8 + (lane >> 2)] = p1;
    }
}

// ---- layer 2 scores (H=1, C=128), warp per TWO CSR slots ----------------
__global__ void __launch_bounds__(256)
score2_kernel(const float* __restrict__ We, const float* __restrict__ att,
              const float* __restrict__ ea, int E, int Etot) {
    int t = threadIdx.x;
    int warp = t >> 5, lane = t & 31;
    int pb = (blockIdx.x * 8 + warp) * 2;
    if (pb >= Etot) return;
    bool v1 = (pb + 1 < Etot);

    int k0 = g_eid[pb];
    int k1 = v1 ? g_eid[pb + 1] : k0;
    int s0, d0, s1, d1;
    float ev0, ev1;
    if (k0 < E) { s0 = g_src[k0]; d0 = g_dst[k0]; ev0 = ea[k0]; }
    else        { s0 = d0 = k0 - E; ev0 = g_ealoop[s0]; }
    if (k1 < E) { s1 = g_src[k1]; d1 = g_dst[k1]; ev1 = ea[k1]; }
    else        { s1 = d1 = k1 - E; ev1 = g_ealoop[s1]; }

    const int c0 = lane * 4;
    float4 Wv = *(const float4*)&We[c0];
    float4 Av = *(const float4*)&att[c0];
    float4 l0 = *(const float4*)&g_xl2[(size_t)s0 * 128 + c0];
    float4 r0 = *(const float4*)&g_xr2[(size_t)d0 * 128 + c0];
    float4 l1 = *(const float4*)&g_xl2[(size_t)s1 * 128 + c0];
    float4 r1 = *(const float4*)&g_xr2[(size_t)d1 * 128 + c0];

    float p0, p1;
    {
        float a = l0.x + r0.x + ev0 * Wv.x; a = fmaxf(a,0.f) + 0.2f*fminf(a,0.f);
        float b = l0.y + r0.y + ev0 * Wv.y; b = fmaxf(b,0.f) + 0.2f*fminf(b,0.f);
        float c = l0.z + r0.z + ev0 * Wv.z; c = fmaxf(c,0.f) + 0.2f*fminf(c,0.f);
        float e = l0.w + r0.w + ev0 * Wv.w; e = fmaxf(e,0.f) + 0.2f*fminf(e,0.f);
        p0 = a*Av.x + b*Av.y + c*Av.z + e*Av.w;
    }
    {
        float a = l1.x + r1.x + ev1 * Wv.x; a = fmaxf(a,0.f) + 0.2f*fminf(a,0.f);
        float b = l1.y + r1.y + ev1 * Wv.y; b = fmaxf(b,0.f) + 0.2f*fminf(b,0.f);
        float c = l1.z + r1.z + ev1 * Wv.z; c = fmaxf(c,0.f) + 0.2f*fminf(c,0.f);
        float e = l1.w + r1.w + ev1 * Wv.w; e = fmaxf(e,0.f) + 0.2f*fminf(e,0.f);
        p1 = a*Av.x + b*Av.y + c*Av.z + e*Av.w;
    }
    #pragma unroll
    for (int o = 16; o; o >>= 1) {
        p0 += __shfl_xor_sync(0xffffffffu, p0, o);
        p1 += __shfl_xor_sync(0xffffffffu, p1, o);
    }
    if (lane == 0) {
        g_s2[pb] = p0;
        if (v1) g_s2[pb + 1] = p1;
    }
}

// ---------- layer 1 aggregation: one block (256 thr) per node ------------
__global__ void agg1_kernel(const float* __restrict__ bias, int E) {
    const int CH = 64;
    __shared__ float mx[8], idn[8];
    __shared__ float ash[CH * 8];
    __shared__ int   ssh[CH];
    int j = blockIdx.x;
    int off = g_off[j], end = g_off[j + 1];
    int d = end - off;
    int t = threadIdx.x;
    int h = t >> 5, lane = t & 31;

    // online softmax stats per head (warp h owns head h)
    float m = -1e30f, sum = 0.f;
    for (int idx = lane; idx < d; idx += 32) {
        float sv = g_s1[(size_t)(off + idx) * 8 + h];
        if (sv > m) { sum = sum * __expf(m - sv) + 1.0f; m = sv; }
        else        { sum += __expf(sv - m); }
    }
    #pragma unroll
    for (int o = 16; o; o >>= 1) {
        float m2 = __shfl_xor_sync(0xffffffffu, m, o);
        float s2 = __shfl_xor_sync(0xffffffffu, sum, o);
        float nm = fmaxf(m, m2);
        sum = sum * __expf(m - nm) + s2 * __expf(m2 - nm);
        m = nm;
    }
    if (lane == 0) { mx[h] = m; idn[h] = 1.0f / (sum + 1e-16f); }
    __syncthreads();

    float accv = 0.f;
    for (int cs = 0; cs < d; cs += CH) {
        int cl = min(CH, d - cs);
        for (int i = t; i < cl * 8; i += 256) {
            float sv = g_s1[(size_t)(off + cs) * 8 + i];
            int hh = i & 7;
            ash[i] = __expf(sv - mx[hh]) * idn[hh];
        }
        for (int i = t; i < cl; i += 256) {
            int k = g_eid[off + cs + i];
            ssh[i] = (k < E) ? g_src[k] : (k - E);
        }
        __syncthreads();
        #pragma unroll 8
        for (int el = 0; el < cl; el++) {
            float a = ash[el * 8 + h];
            accv += a * g_xl1[(size_t)ssh[el] * 256 + h * 32 + lane];
        }
        __syncthreads();
    }
    int c = h * 32 + lane;
    g_h1[(size_t)j * 256 + c] = fmaxf(accv + bias[c], 0.f);
}

// ---------- layer 2 aggregation + mean pool: block (128 thr) per node ----
__global__ void agg2_kernel(const float* __restrict__ bias, int E) {
    __shared__ float wm[4], ws[4];
    __shared__ float M0sh, IVsh;
    __shared__ float ash[128];
    __shared__ int   ssh[128];
    int j = blockIdx.x;
    int off = g_off[j], end = g_off[j + 1];
    int d = end - off;
    int t = threadIdx.x;
    int w = t >> 5, lane = t & 31;

    float m = -1e30f, sum = 0.f;
    for (int idx = t; idx < d; idx += 128) {
        float sv = g_s2[off + idx];
        if (sv > m) { sum = sum * __expf(m - sv) + 1.0f; m = sv; }
        else        { sum += __expf(sv - m); }
    }
    #pragma unroll
    for (int o = 16; o; o >>= 1) {
        float m2 = __shfl_xor_sync(0xffffffffu, m, o);
        float s2 = __shfl_xor_sync(0xffffffffu, sum, o);
        float nm = fmaxf(m, m2);
        sum = sum * __expf(m - nm) + s2 * __expf(m2 - nm);
        m = nm;
    }
    if (lane == 0) { wm[w] = m; ws[w] = sum; }
    __syncthreads();
    if (t == 0) {
        float M0 = fmaxf(fmaxf(wm[0], wm[1]), fmaxf(wm[2], wm[3]));
        float S0 = ws[0] * __expf(wm[0] - M0) + ws[1] * __expf(wm[1] - M0)
                 + ws[2] * __expf(wm[2] - M0) + ws[3] * __expf(wm[3] - M0);
        M0sh = M0;
        IVsh = 1.0f / (S0 + 1e-16f);
    }
    __syncthreads();
    float M0 = M0sh, invd = IVsh;

    float accv = 0.f;
    for (int cs = 0; cs < d; cs += 128) {
        int cl = min(128, d - cs);
        if (t < cl) {
            ash[t] = __expf(g_s2[off + cs + t] - M0) * invd;
            int k = g_eid[off + cs + t];
            ssh[t] = (k < E) ? g_src[k] : (k - E);
        }
        __syncthreads();
        #pragma unroll 8
        for (int el = 0; el < cl; el++)
            accv += ash[el] * g_xl2[(size_t)ssh[el] * 128 + t];
        __syncthreads();
    }
    float val = fmaxf(accv + bias[t], 0.f);
    atomicAdd(&g_pool[t], val);
}

// ---------------- final: mean, softmax, sigmoid(alpha) -------------------
__global__ void final_kernel(const float* __restrict__ alpha_in,
                             float* __restrict__ out, int out_size, float invN) {
    __shared__ float sh[128];
    int t = threadIdx.x;
    float v = g_pool[t] * invN;
    sh[t] = v;
    __syncthreads();
    for (int o = 64; o; o >>= 1) {
        if (t < o) sh[t] = fmaxf(sh[t], sh[t + o]);
        __syncthreads();
    }
    float mx = sh[0];
    __syncthreads();
    float e = __expf(v - mx);
    sh[t] = e;
    __syncthreads();
    for (int o = 64; o; o >>= 1) {
        if (t < o) sh[t] += sh[t + o];
        __syncthreads();
    }
    float s = sh[0];
    out[t] = e / s;
    if (t == 0 && out_size > 128)
        out[128] = 1.0f / (1.0f + __expf(-alpha_in[0]));
}

// -------------------------------------------------------------------------
extern "C" void kernel_launch(void* const* d_in, const int* in_sizes, int n_in,
                              void* d_out, int out_size) {
    (void)n_in;
    const float* x     = (const float*)d_in[0];
    const int*   eidx  = (const int*)d_in[1];   // int32 or int64 (detected)
    const float* ea    = (const float*)d_in[2];
    const float* W1l   = (const float*)d_in[3];
    const float* b1l   = (const float*)d_in[4];
    const float* W1r   = (const float*)d_in[5];
    const float* b1r   = (const float*)d_in[6];
    const float* We1   = (const float*)d_in[7];
    const float* att1  = (const float*)d_in[8];
    const float* bias1 = (const float*)d_in[9];
    const float* W2l   = (const float*)d_in[10];
    const float* b2l   = (const float*)d_in[11];
    const float* W2r   = (const float*)d_in[12];
    const float* b2r   = (const float*)d_in[13];
    const float* We2   = (const float*)d_in[14];
    const float* att2  = (const float*)d_in[15];
    const float* bias2 = (const float*)d_in[16];
    const float* alpha = (const float*)d_in[17];
    float* out = (float*)d_out;

    int N = in_sizes[0] / 128;
    if (N > NMAX) N = NMAX;
    int E = in_sizes[1] / 2;
    if (E > EMAX) E = EMAX;
    int Etot = E + N;

    int mb = (N + 127) / 128;

    // preprocessing + layer-1 GEMM placed 4th so ncu (-s 5) captures it
    init_kernel<<<(N + 255) / 256, 256>>>(N);
    detect_kernel<<<1, 32>>>(eidx, E);
    extract_kernel<<<(E + 255) / 256, 256>>>(eidx, ea, E);
    gemm_bias_dual<<<dim3(mb, 2, 2), 256>>>(x, -1, W1l, b1l, 0, W1r, b1r, 1,
                                            N, 128, 256);           // 4th launch
    ealoop_kernel<<<(N + 255) / 256, 256>>>(N);
    scan_kernel<<<1, 1024>>>(N);
    scatter_kernel<<<(Etot + 255) / 256, 256>>>(E, N);

    // layer 1 edge pipeline (2 edges per warp)
    score1_kernel<<<(Etot + 15) / 16, 256>>>(We1, att1, ea, E, Etot);
    agg1_kernel<<<N, 256>>>(bias1, E);

    // layer 2
    gemm_bias_dual<<<dim3(mb, 1, 2), 256>>>(nullptr, 2, W2l, b2l, 3, W2r, b2r, 4,
                                            N, 256, 128);
    score2_kernel<<<(Etot + 15) / 16, 256>>>(We2, att2, ea, E, Etot);
    agg2_kernel<<<N, 128>>>(bias2, E);

    // pooled softmax + sigmoid(alpha)
    final_kernel<<<1, 128>>>(alpha, out, out_size, 1.0f / (float)N);
}

// round 10
// speedup vs baseline: 1.4193x; 1.1399x over previous
#include <cuda_runtime.h>
#include <math.h>

// Problem constants (validated against in_sizes at launch).
#define NMAX 20000
#define EMAX 640000
#define ETOTMAX (EMAX + NMAX)
#define SCAP 384   // edge chunk per node (avg degree ~33; chunked for any degree)

// ---------------- device scratch (no allocations allowed) ----------------
__device__ int   g_is64;
__device__ int   g_src[EMAX];
__device__ int   g_dst[EMAX];
__device__ float g_easum[NMAX];
__device__ float g_ealoop[NMAX];
__device__ int   g_cnt[NMAX];
__device__ int   g_cursor[NMAX];
__device__ int   g_off[NMAX + 1];
__device__ int   g_eid[ETOTMAX];
__device__ float g_xl1[NMAX * 256];
__device__ float g_xr1[NMAX * 256];
__device__ float g_h1[NMAX * 256];
__device__ float g_xl2[NMAX * 128];
__device__ float g_xr2[NMAX * 128];
__device__ float g_pool[128];

// Device-side scratch selector (avoids any host-side symbol queries).
__device__ __forceinline__ float* buf_sel(int code) {
    switch (code) {
        case 0:  return g_xl1;
        case 1:  return g_xr1;
        case 2:  return g_h1;
        case 3:  return g_xl2;
        default: return g_xr2;
    }
}

// ---------------- init (graph replays reuse accumulators) ----------------
__global__ void init_kernel(int n) {
    int i = blockIdx.x * blockDim.x + threadIdx.x;
    if (i < n) {
        g_easum[i]  = 0.f;
        g_cursor[i] = 0;
        g_cnt[i]    = 1;   // self-loop pre-counted
    }
    if (i < 128) g_pool[i] = 0.f;
}

// Detect whether edge_index is stored as int64 (little-endian: high words 0)
__global__ void detect_kernel(const int* __restrict__ raw, int E) {
    int nz = 0;
    int lim = (E < 64) ? E : 64;
    for (int i = threadIdx.x; i < lim; i += 32)
        if (raw[2 * i + 1] != 0) nz = 1;
    nz = __any_sync(0xffffffffu, nz);
    if (threadIdx.x == 0) g_is64 = nz ? 0 : 1;
}

// Extract src/dst, accumulate per-dst edge_attr sum / CSR counts
__global__ void extract_kernel(const int* __restrict__ raw,
                               const float* __restrict__ ea, int E) {
    int e = blockIdx.x * blockDim.x + threadIdx.x;
    if (e >= E) return;
    int is64 = g_is64;
    int s = is64 ? raw[2 * e]       : raw[e];
    int d = is64 ? raw[2 * (E + e)] : raw[E + e];
    g_src[e] = s;
    g_dst[e] = d;
    atomicAdd(&g_easum[d], ea[e]);
    atomicAdd(&g_cnt[d], 1);
}

__global__ void ealoop_kernel(int n) {
    int i = blockIdx.x * blockDim.x + threadIdx.x;
    if (i < n) {
        float deg = (float)(g_cnt[i] - 1);   // real incoming degree
        g_ealoop[i] = g_easum[i] / fmaxf(deg, 1.0f);
    }
}

// 3-level shuffle scan: 20 elems/thread -> warp scan -> 1 warp over 32 sums.
__global__ void scan_kernel(int n) {
    const int C = 20;                 // 1024*20 = 20480 >= NMAX
    __shared__ int wsum[32];
    __shared__ int gtot;
    int t = threadIdx.x;
    int lane = t & 31, warp = t >> 5;
    int base = t * C;

    int vex[C];
    int run = 0;
    #pragma unroll
    for (int i = 0; i < C; i++) {
        int idx = base + i;
        int x = (idx < n) ? g_cnt[idx] : 0;
        vex[i] = run;                 // exclusive local prefix
        run += x;
    }
    int incl = run;
    #pragma unroll
    for (int o = 1; o < 32; o <<= 1) {
        int u = __shfl_up_sync(0xffffffffu, incl, o);
        if (lane >= o) incl += u;
    }
    if (lane == 31) wsum[warp] = incl;
    __syncthreads();
    if (warp == 0) {
        int s = wsum[lane];
        int si = s;
        #pragma unroll
        for (int o = 1; o < 32; o <<= 1) {
            int u = __shfl_up_sync(0xffffffffu, si, o);
            if (lane >= o) si += u;
        }
        wsum[lane] = si - s;          // exclusive warp prefix
        if (lane == 31) gtot = si;
    }
    __syncthreads();
    int pre = wsum[warp] + (incl - run);
    #pragma unroll
    for (int i = 0; i < C; i++) {
        int idx = base + i;
        if (idx < n) g_off[idx] = pre + vex[i];
    }
    if (t == 0) g_off[n] = gtot;
}

// Fill CSR edge-id lists (edge k<E: real edge; k>=E: self loop of node k-E)
__global__ void scatter_kernel(int E, int n) {
    int k = blockIdx.x * blockDim.x + threadIdx.x;
    int tot = E + n;
    if (k >= tot) return;
    int d = (k < E) ? g_dst[k] : (k - E);
    int pos = g_off[d] + atomicAdd(&g_cursor[d], 1);
    g_eid[pos] = k;
}

// ---- fp32 SGEMM 128x128, 8x8/thread, k-panel 8, double-buffered smem ----
__global__ void __launch_bounds__(256, 2)
gemm_bias_dual(const float* __restrict__ Ain, int Acode,
               const float* __restrict__ W0, const float* __restrict__ b0, int C0code,
               const float* __restrict__ W1, const float* __restrict__ b1, int C1code,
               int M, int K, int Nn) {
    const float* A = (Acode >= 0) ? buf_sel(Acode) : Ain;
    const float* W    = (blockIdx.z == 0) ? W0 : W1;
    const float* bias = (blockIdx.z == 0) ? b0 : b1;
    float* C = buf_sel(blockIdx.z == 0 ? C0code : C1code);

    __shared__ __align__(16) float As[2][8][132];   // transposed A panel
    __shared__ __align__(16) float Bs[2][8][128];

    const int tid = threadIdx.x;
    const int tx = tid & 15, ty = tid >> 4;
    const int tm0 = ty * 8, tn0 = tx * 8;
    const int row0 = blockIdx.x * 128, col0 = blockIdx.y * 128;

    const int arow = tid >> 1;            // 0..127
    const int acol = (tid & 1) * 4;       // 0 or 4
    const int b_r = tid >> 5;             // 0..7
    const int b_c = (tid & 31) * 4;       // 0..124

    const int a_gr = row0 + arow;
    const bool a_ok = (a_gr < M);
    const int P = K >> 3;

    float acc[8][8];
    #pragma unroll
    for (int i = 0; i < 8; i++)
        #pragma unroll
        for (int j = 0; j < 8; j++) acc[i][j] = 0.f;

    // preload panel 0
    {
        float4 av = make_float4(0.f, 0.f, 0.f, 0.f);
        if (a_ok) av = *(const float4*)&A[(size_t)a_gr * K + acol];
        float4 bv = *(const float4*)&W[(size_t)b_r * Nn + col0 + b_c];
        As[0][acol + 0][arow] = av.x;
        As[0][acol + 1][arow] = av.y;
        As[0][acol + 2][arow] = av.z;
        As[0][acol + 3][arow] = av.w;
        *(float4*)&Bs[0][b_r][b_c] = bv;
    }
    __syncthreads();

    for (int p = 0; p < P; p++) {
        const int cur = p & 1;
        const bool more = (p + 1 < P);
        float4 av_n = make_float4(0.f, 0.f, 0.f, 0.f), bv_n;
        if (more) {
            int k0 = (p + 1) * 8;
            if (a_ok) av_n = *(const float4*)&A[(size_t)a_gr * K + k0 + acol];
            bv_n = *(const float4*)&W[(size_t)(k0 + b_r) * Nn + col0 + b_c];
        }

        #pragma unroll
        for (int kk = 0; kk < 8; kk++) {
            float a[8], b[8];
            *(float4*)&a[0] = *(const float4*)&As[cur][kk][tm0];
            *(float4*)&a[4] = *(const float4*)&As[cur][kk][tm0 + 4];
            *(float4*)&b[0] = *(const float4*)&Bs[cur][kk][tn0];
            *(float4*)&b[4] = *(const float4*)&Bs[cur][kk][tn0 + 4];
            #pragma unroll
            for (int i = 0; i < 8; i++)
                #pragma unroll
                for (int j = 0; j < 8; j++)
                    acc[i][j] += a[i] * b[j];
        }

        if (more) {
            const int nxt = cur ^ 1;
            As[nxt][acol + 0][arow] = av_n.x;
            As[nxt][acol + 1][arow] = av_n.y;
            As[nxt][acol + 2][arow] = av_n.z;
            As[nxt][acol + 3][arow] = av_n.w;
            *(float4*)&Bs[nxt][b_r][b_c] = bv_n;
        }
        __syncthreads();
    }

    float bcache[8];
    #pragma unroll
    for (int j = 0; j < 8; j++) bcache[j] = bias[col0 + tn0 + j];
    #pragma unroll
    for (int i = 0; i < 8; i++) {
        int gr = row0 + tm0 + i;
        if (gr >= M) continue;
        float4 v0 = make_float4(acc[i][0] + bcache[0], acc[i][1] + bcache[1],
                                acc[i][2] + bcache[2], acc[i][3] + bcache[3]);
        float4 v1 = make_float4(acc[i][4] + bcache[4], acc[i][5] + bcache[5],
                                acc[i][6] + bcache[6], acc[i][7] + bcache[7]);
        *(float4*)&C[(size_t)gr * Nn + col0 + tn0]     = v0;
        *(float4*)&C[(size_t)gr * Nn + col0 + tn0 + 4] = v1;
    }
}

// ===== fused layer-1: per-node block, parallel scoring into smem =========
// 256 threads = 8 warps. Phase A: warp w scores edges w, w+8,... (lane owns
// 8 channels; head h = lanes [4h,4h+4)). Phase B: warp h = head h chunk
// max/sum, scores -> weights in place. Phase C: thread owns channel
// c = warp*32+lane, gathers xl1 with weights. Chunked with rescaling.
__global__ void __launch_bounds__(256)
fused1_kernel(const float* __restrict__ We, const float* __restrict__ att,
              const float* __restrict__ bias, const float* __restrict__ ea,
              int E) {
    __shared__ float s[SCAP * 8];
    __shared__ int   ssrc[SCAP];
    __shared__ float sea[SCAP];
    __shared__ float mh[8], sumh[8];

    const int j = blockIdx.x;
    const int off = g_off[j];
    const int d = g_off[j + 1] - off;
    const int t = threadIdx.x;
    const int warp = t >> 5, lane = t & 31;
    const float eal = g_ealoop[j];

    if (t < 8) { mh[t] = -1e30f; sumh[t] = 0.f; }

    // phase-A per-lane constants (lane owns channels [8*lane, 8*lane+8))
    const int c0 = lane * 8;
    const float4 W0 = *(const float4*)&We[c0],  W1 = *(const float4*)&We[c0 + 4];
    const float4 A0 = *(const float4*)&att[c0], A1 = *(const float4*)&att[c0 + 4];
    const float4 xr0 = *(const float4*)&g_xr1[(size_t)j * 256 + c0];
    const float4 xr1 = *(const float4*)&g_xr1[(size_t)j * 256 + c0 + 4];

    float accv = 0.f;   // phase-C channel c = warp*32 + lane

    for (int cs = 0; cs < d; cs += SCAP) {
        const int cl = min(SCAP, d - cs);
        for (int i = t; i < cl; i += 256) {
            int k = g_eid[off + cs + i];
            if (k < E) { ssrc[i] = g_src[k]; sea[i] = ea[k]; }
            else       { ssrc[i] = j;        sea[i] = eal;  }
        }
        __syncthreads();

        // ---- phase A: parallel scoring, 2 edges in flight per warp ----
        for (int e = warp; e < cl; e += 16) {
            int e2 = e + 8;
            bool has2 = (e2 < cl);
            int   sA = ssrc[e];
            float vA = sea[e];
            int   sB = has2 ? ssrc[e2] : sA;
            float vB = has2 ? sea[e2] : vA;
            float4 a0 = *(const float4*)&g_xl1[(size_t)sA * 256 + c0];
            float4 a1 = *(const float4*)&g_xl1[(size_t)sA * 256 + c0 + 4];
            float4 b0 = *(const float4*)&g_xl1[(size_t)sB * 256 + c0];
            float4 b1 = *(const float4*)&g_xl1[(size_t)sB * 256 + c0 + 4];
            float pA, pB;
            {
                float a = a0.x + xr0.x + vA * W0.x; a = fmaxf(a,0.f) + 0.2f*fminf(a,0.f);
                float b = a0.y + xr0.y + vA * W0.y; b = fmaxf(b,0.f) + 0.2f*fminf(b,0.f);
                float c = a0.z + xr0.z + vA * W0.z; c = fmaxf(c,0.f) + 0.2f*fminf(c,0.f);
                float g = a0.w + xr0.w + vA * W0.w; g = fmaxf(g,0.f) + 0.2f*fminf(g,0.f);
                pA = a*A0.x + b*A0.y + c*A0.z + g*A0.w;
                a = a1.x + xr1.x + vA * W1.x; a = fmaxf(a,0.f) + 0.2f*fminf(a,0.f);
                b = a1.y + xr1.y + vA * W1.y; b = fmaxf(b,0.f) + 0.2f*fminf(b,0.f);
                c = a1.z + xr1.z + vA * W1.z; c = fmaxf(c,0.f) + 0.2f*fminf(c,0.f);
                g = a1.w + xr1.w + vA * W1.w; g = fmaxf(g,0.f) + 0.2f*fminf(g,0.f);
                pA += a*A1.x + b*A1.y + c*A1.z + g*A1.w;
            }
            {
                float a = b0.x + xr0.x + vB * W0.x; a = fmaxf(a,0.f) + 0.2f*fminf(a,0.f);
                float b = b0.y + xr0.y + vB * W0.y; b = fmaxf(b,0.f) + 0.2f*fminf(b,0.f);
                float c = b0.z + xr0.z + vB * W0.z; c = fmaxf(c,0.f) + 0.2f*fminf(c,0.f);
                float g = b0.w + xr0.w + vB * W0.w; g = fmaxf(g,0.f) + 0.2f*fminf(g,0.f);
                pB = a*A0.x + b*A0.y + c*A0.z + g*A0.w;
                a = b1.x + xr1.x + vB * W1.x; a = fmaxf(a,0.f) + 0.2f*fminf(a,0.f);
                b = b1.y + xr1.y + vB * W1.y; b = fmaxf(b,0.f) + 0.2f*fminf(b,0.f);
                c = b1.z + xr1.z + vB * W1.z; c = fmaxf(c,0.f) + 0.2f*fminf(c,0.f);
                g = b1.w + xr1.w + vB * W1.w; g = fmaxf(g,0.f) + 0.2f*fminf(g,0.f);
                pB += a*A1.x + b*A1.y + c*A1.z + g*A1.w;
            }
            pA += __shfl_xor_sync(0xffffffffu, pA, 1);
            pB += __shfl_xor_sync(0xffffffffu, pB, 1);
            pA += __shfl_xor_sync(0xffffffffu, pA, 2);
            pB += __shfl_xor_sync(0xffffffffu, pB, 2);
            if ((lane & 3) == 0) {
                s[e * 8 + (lane >> 2)] = pA;
                if (has2) s[e2 * 8 + (lane >> 2)] = pB;
            }
        }
        __syncthreads();

        // ---- phase B: per-head chunk max/sum, scores -> weights --------
        const int h = warp;
        float cmx = -1e30f;
        for (int e = lane; e < cl; e += 32) cmx = fmaxf(cmx, s[e * 8 + h]);
        #pragma unroll
        for (int o = 16; o; o >>= 1)
            cmx = fmaxf(cmx, __shfl_xor_sync(0xffffffffu, cmx, o));
        float m_o = mh[h];
        float nm = fmaxf(m_o, cmx);
        float csum = 0.f;
        for (int e = lane; e < cl; e += 32) {
            float w = __expf(s[e * 8 + h] - nm);
            s[e * 8 + h] = w;
            csum += w;
        }
        #pragma unroll
        for (int o = 16; o; o >>= 1) csum += __shfl_xor_sync(0xffffffffu, csum, o);
        float fac = __expf(m_o - nm);
        accv *= fac;
        if (lane == 0) { sumh[h] = sumh[h] * fac + csum; mh[h] = nm; }
        __syncwarp();

        // ---- phase C: gather-aggregate (warp reads only its own head) --
        #pragma unroll 8
        for (int e = 0; e < cl; e++)
            accv += s[e * 8 + h] * g_xl1[(size_t)ssrc[e] * 256 + h * 32 + lane];
        __syncthreads();
    }

    const int h = warp;
    float inv = 1.0f / (sumh[h] + 1e-16f);
    int c = h * 32 + lane;
    g_h1[(size_t)j * 256 + c] = fmaxf(accv * inv + bias[c], 0.f);
}

// ===== fused layer-2: per-node block (128 thr), single head ==============
__global__ void __launch_bounds__(128)
fused2_kernel(const float* __restrict__ We, const float* __restrict__ att,
              const float* __restrict__ bias, const float* __restrict__ ea,
              int E) {
    __shared__ float s[SCAP];
    __shared__ int   ssrc[SCAP];
    __shared__ float sea[SCAP];
    __shared__ float red[4];
    __shared__ float m_run_s, sum_run_s, nm_s, fac_s;

    const int j = blockIdx.x;
    const int off = g_off[j];
    const int d = g_off[j + 1] - off;
    const int t = threadIdx.x;
    const int warp = t >> 5, lane = t & 31;
    const float eal = g_ealoop[j];

    if (t == 0) { m_run_s = -1e30f; sum_run_s = 0.f; }

    const int c0 = lane * 4;
    const float4 Wv = *(const float4*)&We[c0];
    const float4 Av = *(const float4*)&att[c0];
    const float4 xr = *(const float4*)&g_xr2[(size_t)j * 128 + c0];

    float accv = 0.f;   // channel = t

    for (int cs = 0; cs < d; cs += SCAP) {
        const int cl = min(SCAP, d - cs);
        for (int i = t; i < cl; i += 128) {
            int k = g_eid[off + cs + i];
            if (k < E) { ssrc[i] = g_src[k]; sea[i] = ea[k]; }
            else       { ssrc[i] = j;        sea[i] = eal;  }
        }
        __syncthreads();

        // phase A: warp per edge (strided 4), 2 in flight
        for (int e = warp; e < cl; e += 8) {
            int e2 = e + 4;
            bool has2 = (e2 < cl);
            int   sA = ssrc[e];
            float vA = sea[e];
            int   sB = has2 ? ssrc[e2] : sA;
            float vB = has2 ? sea[e2] : vA;
            float4 lA = *(const float4*)&g_xl2[(size_t)sA * 128 + c0];
            float4 lB = *(const float4*)&g_xl2[(size_t)sB * 128 + c0];
            float pA, pB;
            {
                float a = lA.x + xr.x + vA * Wv.x; a = fmaxf(a,0.f) + 0.2f*fminf(a,0.f);
                float b = lA.y + xr.y + vA * Wv.y; b = fmaxf(b,0.f) + 0.2f*fminf(b,0.f);
                float c = lA.z + xr.z + vA * Wv.z; c = fmaxf(c,0.f) + 0.2f*fminf(c,0.f);
                float g = lA.w + xr.w + vA * Wv.w; g = fmaxf(g,0.f) + 0.2f*fminf(g,0.f);
                pA = a*Av.x + b*Av.y + c*Av.z + g*Av.w;
            }
            {
                float a = lB.x + xr.x + vB * Wv.x; a = fmaxf(a,0.f) + 0.2f*fminf(a,0.f);
                float b = lB.y + xr.y + vB * Wv.y; b = fmaxf(b,0.f) + 0.2f*fminf(b,0.f);
                float c = lB.z + xr.z + vB * Wv.z; c = fmaxf(c,0.f) + 0.2f*fminf(c,0.f);
                float g = lB.w + xr.w + vB * Wv.w; g = fmaxf(g,0.f) + 0.2f*fminf(g,0.f);
                pB = a*Av.x + b*Av.y + c*Av.z + g*Av.w;
            }
            #pragma unroll
            for (int o = 16; o; o >>= 1) {
                pA += __shfl_xor_sync(0xffffffffu, pA, o);
                pB += __shfl_xor_sync(0xffffffffu, pB, o);
            }
            if (lane == 0) {
                s[e] = pA;
                if (has2) s[e2] = pB;
            }
        }
        __syncthreads();

        // phase B: block max
        float cmx = -1e30f;
        for (int e = t; e < cl; e += 128) cmx = fmaxf(cmx, s[e]);
        #pragma unroll
        for (int o = 16; o; o >>= 1)
            cmx = fmaxf(cmx, __shfl_xor_sync(0xffffffffu, cmx, o));
        if (lane == 0) red[warp] = cmx;
        __syncthreads();
        if (t == 0) {
            float M = fmaxf(fmaxf(red[0], red[1]), fmaxf(red[2], red[3]));
            float nm = fmaxf(m_run_s, M);
            nm_s = nm;
            fac_s = __expf(m_run_s - nm);
            m_run_s = nm;
        }
        __syncthreads();
        float nm = nm_s;
        // weights in place + block sum
        float csum = 0.f;
        for (int e = t; e < cl; e += 128) {
            float w = __expf(s[e] - nm);
            s[e] = w;
            csum += w;
        }
        #pragma unroll
        for (int o = 16; o; o >>= 1) csum += __shfl_xor_sync(0xffffffffu, csum, o);
        if (lane == 0) red[warp] = csum;
        __syncthreads();
        if (t == 0)
            sum_run_s = sum_run_s * fac_s + (red[0] + red[1] + red[2] + red[3]);
        float fac = fac_s;
        accv *= fac;
        __syncthreads();   // weights visible to all warps before gather

        // phase C: gather-aggregate (channel = t)
        #pragma unroll 8
        for (int e = 0; e < cl; e++)
            accv += s[e] * g_xl2[(size_t)ssrc[e] * 128 + t];
        __syncthreads();
    }

    float inv = 1.0f / (sum_run_s + 1e-16f);
    float val = fmaxf(accv * inv + bias[t], 0.f);
    atomicAdd(&g_pool[t], val);
}

// ---------------- final: mean, softmax, sigmoid(alpha) -------------------
__global__ void final_kernel(const float* __restrict__ alpha_in,
                             float* __restrict__ out, int out_size, float invN) {
    __shared__ float sh[128];
    int t = threadIdx.x;
    float v = g_pool[t] * invN;
    sh[t] = v;
    __syncthreads();
    for (int o = 64; o; o >>= 1) {
        if (t < o) sh[t] = fmaxf(sh[t], sh[t + o]);
        __syncthreads();
    }
    float mx = sh[0];
    __syncthreads();
    float e = __expf(v - mx);
    sh[t] = e;
    __syncthreads();
    for (int o = 64; o; o >>= 1) {
        if (t < o) sh[t] += sh[t + o];
        __syncthreads();
    }
    float s = sh[0];
    out[t] = e / s;
    if (t == 0 && out_size > 128)
        out[128] = 1.0f / (1.0f + __expf(-alpha_in[0]));
}

// -------------------------------------------------------------------------
extern "C" void kernel_launch(void* const* d_in, const int* in_sizes, int n_in,
                              void* d_out, int out_size) {
    (void)n_in;
    const float* x     = (const float*)d_in[0];
    const int*   eidx  = (const int*)d_in[1];   // int32 or int64 (detected)
    const float* ea    = (const float*)d_in[2];
    const float* W1l   = (const float*)d_in[3];
    const float* b1l   = (const float*)d_in[4];
    const float* W1r   = (const float*)d_in[5];
    const float* b1r   = (const float*)d_in[6];
    const float* We1   = (const float*)d_in[7];
    const float* att1  = (const float*)d_in[8];
    const float* bias1 = (const float*)d_in[9];
    const float* W2l   = (const float*)d_in[10];
    const float* b2l   = (const float*)d_in[11];
    const float* W2r   = (const float*)d_in[12];
    const float* b2r   = (const float*)d_in[13];
    const float* We2   = (const float*)d_in[14];
    const float* att2  = (const float*)d_in[15];
    const float* bias2 = (const float*)d_in[16];
    const float* alpha = (const float*)d_in[17];
    float* out = (float*)d_out;

    int N = in_sizes[0] / 128;
    if (N > NMAX) N = NMAX;
    int E = in_sizes[1] / 2;
    if (E > EMAX) E = EMAX;
    int Etot = E + N;
    (void)Etot;

    int mb = (N + 127) / 128;

    // preprocessing + layer-1 GEMM placed 4th so ncu (-s 5) captures it
    init_kernel<<<(N + 255) / 256, 256>>>(N);
    detect_kernel<<<1, 32>>>(eidx, E);
    extract_kernel<<<(E + 255) / 256, 256>>>(eidx, ea, E);
    gemm_bias_dual<<<dim3(mb, 2, 2), 256>>>(x, -1, W1l, b1l, 0, W1r, b1r, 1,
                                            N, 128, 256);           // 4th launch
    ealoop_kernel<<<(N + 255) / 256, 256>>>(N);
    scan_kernel<<<1, 1024>>>(N);
    scatter_kernel<<<(Etot + 255) / 256, 256>>>(E, N);

    // layer 1: fused score+softmax+aggregate (per node)
    fused1_kernel<<<N, 256>>>(We1, att1, bias1, ea, E);

    // layer 2
    gemm_bias_dual<<<dim3(mb, 1, 2), 256>>>(nullptr, 2, W2l, b2l, 3, W2r, b2r, 4,
                                            N, 256, 128);
    fused2_kernel<<<N, 128>>>(We2, att2, bias2, ea, E);

    // pooled softmax + sigmoid(alpha)
    final_kernel<<<1, 128>>>(alpha, out, out_size, 1.0f / (float)N);
}